// round 1
// baseline (speedup 1.0000x reference)
#include <cuda_runtime.h>
#include <cstdint>
#include <cstring>

#define BATCH 128
#define ITEMS 8000
#define CONC  128
#define EMB   32
#define TI    64              // items per block
#define NBLK  (ITEMS / TI)    // 125
#define SCS   132             // padded row stride (floats) for stuC in smem
#define QWS   132             // padded row stride for qw in smem

// scratch (allocation-free rule: __device__ globals)
__device__ float g_stuC[BATCH * CONC];
__device__ float g_gsu[BATCH];

__device__ __forceinline__ float sigmoidf(float x) {
    return __fdividef(1.0f, 1.0f + __expf(-x));
}

// ---------------------------------------------------------------------------
// Kernel 1: stuC[b,c] = sigmoid(stu_emb[idx[b]] . w1[c] + b1[c]);  gsu[b]
// ---------------------------------------------------------------------------
__global__ void __launch_bounds__(128) stu_kernel(
    const int*   __restrict__ stu_list,
    const float* __restrict__ stu_emb,
    const float* __restrict__ w1,
    const float* __restrict__ b1,
    const float* __restrict__ gw_stu)
{
    __shared__ float s_w1[CONC * 33];
    __shared__ float s_emb[EMB];
    const int b = blockIdx.x;
    const int t = threadIdx.x;
    const int idx = stu_list[b] - 1;

    for (int j = t; j < CONC * EMB; j += 128) {
        s_w1[(j >> 5) * 33 + (j & 31)] = w1[j];
    }
    if (t < EMB) s_emb[t] = stu_emb[(size_t)idx * EMB + t];
    if (t == 0)  g_gsu[b] = gw_stu[idx];
    __syncthreads();

    float z = b1[t];
#pragma unroll
    for (int k = 0; k < EMB; k++) z = fmaf(s_emb[k], s_w1[t * 33 + k], z);
    g_stuC[b * CONC + t] = sigmoidf(z);
}

// ---------------------------------------------------------------------------
// Kernel 2: per 64-item tile — itemC + qw + per-item scalars, then the
// 128x64x128 GEMM term1 = stuC @ qw^T with packed f32x2 FMAs, fused epilogue.
// ---------------------------------------------------------------------------
__global__ void __launch_bounds__(256, 1) main_kernel(
    const float* __restrict__ item_emb,
    const float* __restrict__ disc,
    const float* __restrict__ Q,
    const float* __restrict__ w1,
    const float* __restrict__ b1,
    const float* __restrict__ wp,
    const float* __restrict__ bp,
    const float* __restrict__ gw_Q,
    const float* __restrict__ w2,
    const float* __restrict__ b2,
    float* __restrict__ out)
{
    extern __shared__ float sm[];
    float* s_stuC = sm;                       // 128*132
    float* s_qw   = s_stuC + BATCH * SCS;     // 64*132
    float* s_w1   = s_qw   + TI * QWS;        // 128*33
    float* s_ie   = s_w1   + CONC * 33;       // 64*33
    float* s_t2p  = s_ie   + TI * 33;         // 64*4
    float* s_qap  = s_t2p  + TI * 4;          // 64*4
    float* s_zc   = s_qap  + TI * 4;          // 64
    float* s_qa   = s_zc   + TI;              // 64
    float* s_disc = s_qa   + TI;              // 64
    float* s_gsu  = s_disc + TI;              // 128

    const int tid = threadIdx.x;
    const int i0  = blockIdx.x * TI;

    // ---- async: g_stuC -> s_stuC (padded rows), overlapped with phase B ----
    for (int j = tid; j < BATCH * (CONC / 4); j += 256) {
        const int r  = j >> 5;     // 32 float4-chunks per row
        const int c4 = j & 31;
        unsigned dst = (unsigned)__cvta_generic_to_shared(s_stuC + r * SCS + c4 * 4);
        const float* src = g_stuC + r * CONC + c4 * 4;
        asm volatile("cp.async.ca.shared.global [%0], [%1], 16;\n" :: "r"(dst), "l"(src));
    }
    asm volatile("cp.async.commit_group;\n" ::: "memory");

    // ---- synchronous smem fills ----
    for (int j = tid; j < CONC * EMB; j += 256)
        s_w1[(j >> 5) * 33 + (j & 31)] = w1[j];
    for (int j = tid; j < TI * EMB; j += 256)
        s_ie[(j >> 5) * 33 + (j & 31)] = item_emb[(size_t)i0 * EMB + j];
    if (tid < BATCH) s_gsu[tid] = g_gsu[tid];
    __syncthreads();

    // ---- phase B: item_conc, qw, per-item reductions ----
    {
        const int c    = tid & 127;
        const int p    = tid >> 7;
        const int lane = tid & 31;
        const int chunk = c >> 5;
        const float wpc = wp[c];
        const float b1c = b1[c];
        const float gqc = gw_Q[c];
        for (int ii = p; ii < TI; ii += 2) {
            float z = b1c;
#pragma unroll
            for (int k = 0; k < EMB; k++)
                z = fmaf(s_ie[ii * 33 + k], s_w1[c * 33 + k], z);
            const float ic  = sigmoidf(z);
            const float qv  = Q[(size_t)(i0 + ii) * CONC + c];
            const float qwv = qv * wpc;
            s_qw[ii * QWS + c] = qwv;
            float prod = qwv * ic;
            float qadj = qv * gqc;
#pragma unroll
            for (int off = 16; off > 0; off >>= 1) {
                prod += __shfl_down_sync(0xffffffffu, prod, off);
                qadj += __shfl_down_sync(0xffffffffu, qadj, off);
            }
            if (lane == 0) {
                s_t2p[ii * 4 + chunk] = prod;
                s_qap[ii * 4 + chunk] = qadj;
            }
        }
    }
    __syncthreads();
    if (tid < TI) {
        const float t2 = s_t2p[tid * 4] + s_t2p[tid * 4 + 1] +
                         s_t2p[tid * 4 + 2] + s_t2p[tid * 4 + 3];
        const float qa = s_qap[tid * 4] + s_qap[tid * 4 + 1] +
                         s_qap[tid * 4 + 2] + s_qap[tid * 4 + 3];
        const float d  = disc[i0 + tid];
        s_disc[tid] = d;
        s_zc[tid]   = fmaf(-d, t2, bp[0]);
        s_qa[tid]   = qa;
    }
    asm volatile("cp.async.wait_group 0;\n" ::: "memory");
    __syncthreads();

    // ---- phase C: term1 = stuC @ qw^T, thread tile 8(b) x 4(i) ----
    const int tx = tid & 15;   // i-group: i = tx + 16v
    const int ty = tid >> 4;   // b-group: b = ty + 16u
    const float w2v = w2[0];
    const float b2v = b2[0];

    unsigned long long acc[8][4];
#pragma unroll
    for (int u = 0; u < 8; u++)
#pragma unroll
        for (int v = 0; v < 4; v++) acc[u][v] = 0ull;

    const float* pa = s_stuC + ty * SCS;
    const float* pq = s_qw   + tx * QWS;
    for (int c = 0; c < CONC; c += 4) {
        ulonglong2 a[8], q[4];
#pragma unroll
        for (int u = 0; u < 8; u++)
            a[u] = *(const ulonglong2*)(pa + u * 16 * SCS + c);
#pragma unroll
        for (int v = 0; v < 4; v++)
            q[v] = *(const ulonglong2*)(pq + v * 16 * QWS + c);
#pragma unroll
        for (int u = 0; u < 8; u++)
#pragma unroll
            for (int v = 0; v < 4; v++) {
                asm("fma.rn.f32x2 %0, %1, %2, %0;"
                    : "+l"(acc[u][v]) : "l"(a[u].x), "l"(q[v].x));
                asm("fma.rn.f32x2 %0, %1, %2, %0;"
                    : "+l"(acc[u][v]) : "l"(a[u].y), "l"(q[v].y));
            }
    }

    // ---- fused epilogue ----
#pragma unroll
    for (int u = 0; u < 8; u++) {
        const int b = ty + 16 * u;
        const float gs = s_gsu[b];
        float* orow = out + (size_t)b * ITEMS + i0;
#pragma unroll
        for (int v = 0; v < 4; v++) {
            const int il = tx + 16 * v;
            float lo, hi;
            asm("mov.b64 {%0, %1}, %2;" : "=f"(lo), "=f"(hi) : "l"(acc[u][v]));
            const float t1 = lo + hi;
            const float z  = fmaf(s_disc[il], t1, s_zc[il]);
            const float P  = sigmoidf(z);
            const float g1 = sigmoidf(gs + s_qa[il]);
            const float g2 = sigmoidf(fmaf(g1, w2v, b2v));
            orow[il] = g2 + (1.0f - g2) * P;
        }
    }
}

// ---------------------------------------------------------------------------
extern "C" void kernel_launch(void* const* d_in, const int* in_sizes, int n_in,
                              void* d_out, int out_size) {
    const int*   stu_list = (const int*)  d_in[0];
    const float* stu_emb  = (const float*)d_in[1];
    const float* item_emb = (const float*)d_in[2];
    const float* disc     = (const float*)d_in[3];
    const float* Q        = (const float*)d_in[4];
    const float* w1       = (const float*)d_in[5];
    const float* b1       = (const float*)d_in[6];
    const float* wp       = (const float*)d_in[7];
    const float* bp       = (const float*)d_in[8];
    const float* gw_stu   = (const float*)d_in[9];
    const float* gw_Q     = (const float*)d_in[10];
    const float* w2       = (const float*)d_in[11];
    const float* b2       = (const float*)d_in[12];
    float* out = (float*)d_out;

    stu_kernel<<<BATCH, 128>>>(stu_list, stu_emb, w1, b1, gw_stu);

    const size_t smem = (size_t)(BATCH * SCS + TI * QWS + CONC * 33 + TI * 33 +
                                 TI * 4 + TI * 4 + TI + TI + TI + BATCH) * sizeof(float);
    cudaFuncSetAttribute(main_kernel, cudaFuncAttributeMaxDynamicSharedMemorySize,
                         (int)smem);
    main_kernel<<<NBLK, 256, smem>>>(item_emb, disc, Q, w1, b1, wp, bp,
                                     gw_Q, w2, b2, out);
}

// round 2
// speedup vs baseline: 1.2138x; 1.2138x over previous
#include <cuda_runtime.h>
#include <cstdint>

#define BATCH 128
#define ITEMS 8000
#define CONC  128
#define EMB   32
#define TI    64              // items per block
#define NBLK  (ITEMS / TI)    // 125
#define SCS   132             // padded row stride (floats) for stuC in smem
#define QWS   132             // padded row stride for qw in smem
#define W1S   34              // padded row stride for w1 (even -> 8B aligned rows)

// scratch (allocation-free rule: __device__ globals)
__device__ float g_stuC[BATCH * CONC];
__device__ float g_gsu[BATCH];

__device__ __forceinline__ float sigmoidf(float x) {
    return __fdividef(1.0f, 1.0f + __expf(-x));
}

__device__ __forceinline__ void fma2(unsigned long long& acc,
                                     unsigned long long a,
                                     unsigned long long b) {
    asm("fma.rn.f32x2 %0, %1, %2, %0;" : "+l"(acc) : "l"(a), "l"(b));
}

// ---------------------------------------------------------------------------
// Kernel 1: stuC[b,c] = sigmoid(stu_emb[idx[b]] . w1[c] + b1[c]);  gsu[b]
// ---------------------------------------------------------------------------
__global__ void __launch_bounds__(128) stu_kernel(
    const int*   __restrict__ stu_list,
    const float* __restrict__ stu_emb,
    const float* __restrict__ w1,
    const float* __restrict__ b1,
    const float* __restrict__ gw_stu)
{
    __shared__ float s_w1[CONC * 33];
    __shared__ float s_emb[EMB];
    const int b = blockIdx.x;
    const int t = threadIdx.x;
    const int idx = stu_list[b] - 1;

    for (int j = t; j < CONC * EMB; j += 128)
        s_w1[(j >> 5) * 33 + (j & 31)] = w1[j];
    if (t < EMB) s_emb[t] = stu_emb[(size_t)idx * EMB + t];
    if (t == 0)  g_gsu[b] = gw_stu[idx];
    __syncthreads();

    float z = b1[t];
#pragma unroll
    for (int k = 0; k < EMB; k++) z = fmaf(s_emb[k], s_w1[t * 33 + k], z);
    g_stuC[b * CONC + t] = sigmoidf(z);
}

// ---------------------------------------------------------------------------
// Kernel 2 per 64-item tile:
//   phase B: itemC + qw + per-item scalars (w1 row register-resident, f32x2)
//   phase C: term1 = stuC @ qw^T  (128x64x128, thread tile 4b x 8i, f32x2,
//            conflict-free LDS mapping), fused epilogue.
// ---------------------------------------------------------------------------
__global__ void __launch_bounds__(256, 1) main_kernel(
    const float* __restrict__ item_emb,
    const float* __restrict__ disc,
    const float* __restrict__ Q,
    const float* __restrict__ w1,
    const float* __restrict__ b1,
    const float* __restrict__ wp,
    const float* __restrict__ bp,
    const float* __restrict__ gw_Q,
    const float* __restrict__ w2,
    const float* __restrict__ b2,
    float* __restrict__ out)
{
    extern __shared__ float sm[];
    float* s_stuC = sm;                       // 128*132
    float* s_qw   = s_stuC + BATCH * SCS;     // 64*132
    float* s_w1   = s_qw   + TI * QWS;        // 128*34
    float* s_ie   = s_w1   + CONC * W1S;      // 64*32 (linear, 16B aligned)
    float* s_t2p  = s_ie   + TI * EMB;        // 64*4
    float* s_qap  = s_t2p  + TI * 4;          // 64*4
    float* s_zc   = s_qap  + TI * 4;          // 64
    float* s_qa   = s_zc   + TI;              // 64
    float* s_disc = s_qa   + TI;              // 64
    float* s_gsu  = s_disc + TI;              // 128

    const int tid = threadIdx.x;
    const int i0  = blockIdx.x * TI;

    // ---- async: g_stuC -> s_stuC (padded rows), overlapped with phase B ----
    for (int j = tid; j < BATCH * (CONC / 4); j += 256) {
        const int r  = j >> 5;
        const int c4 = j & 31;
        unsigned dst = (unsigned)__cvta_generic_to_shared(s_stuC + r * SCS + c4 * 4);
        const float* src = g_stuC + r * CONC + c4 * 4;
        asm volatile("cp.async.ca.shared.global [%0], [%1], 16;\n" :: "r"(dst), "l"(src));
    }
    asm volatile("cp.async.commit_group;\n" ::: "memory");

    // ---- synchronous smem fills ----
    for (int j = tid; j < CONC * EMB; j += 256)
        s_w1[(j >> 5) * W1S + (j & 31)] = w1[j];
    {   // item_emb tile, linear layout, vectorized
        const float4* src = (const float4*)(item_emb + (size_t)i0 * EMB);
        float4* dst = (float4*)s_ie;
        for (int j = tid; j < TI * EMB / 4; j += 256) dst[j] = src[j];
    }
    if (tid < BATCH) s_gsu[tid] = g_gsu[tid];
    __syncthreads();

    // ---- phase B ----
    {
        const int c     = tid & 127;
        const int p     = tid >> 7;
        const int lane  = tid & 31;
        const int chunk = c >> 5;
        const float wpc = wp[c];
        const float b1c = b1[c];
        const float gqc = gw_Q[c];

        // w1 row c -> registers as 16 packed f32 pairs
        unsigned long long w1r[16];
#pragma unroll
        for (int j = 0; j < 16; j++)
            w1r[j] = *(const unsigned long long*)(s_w1 + c * W1S + 2 * j);

        for (int ii = p; ii < TI; ii += 2) {
            const ulonglong2* ie = (const ulonglong2*)(s_ie + ii * EMB);
            unsigned long long za = 0ull, zb = 0ull;
#pragma unroll
            for (int k = 0; k < 8; k++) {
                ulonglong2 e = ie[k];
                fma2(za, e.x, w1r[2 * k]);
                fma2(zb, e.y, w1r[2 * k + 1]);
            }
            float la, ha, lb, hb;
            asm("mov.b64 {%0, %1}, %2;" : "=f"(la), "=f"(ha) : "l"(za));
            asm("mov.b64 {%0, %1}, %2;" : "=f"(lb), "=f"(hb) : "l"(zb));
            const float z  = (la + ha) + (lb + hb) + b1c;
            const float ic = sigmoidf(z);
            const float qv = Q[(size_t)(i0 + ii) * CONC + c];
            const float qwv = qv * wpc;
            s_qw[ii * QWS + c] = qwv;
            float prod = qwv * ic;
            float qadj = qv * gqc;
#pragma unroll
            for (int off = 16; off > 0; off >>= 1) {
                prod += __shfl_down_sync(0xffffffffu, prod, off);
                qadj += __shfl_down_sync(0xffffffffu, qadj, off);
            }
            if (lane == 0) {
                s_t2p[ii * 4 + chunk] = prod;
                s_qap[ii * 4 + chunk] = qadj;
            }
        }
    }
    __syncthreads();
    if (tid < TI) {
        const float t2 = s_t2p[tid * 4] + s_t2p[tid * 4 + 1] +
                         s_t2p[tid * 4 + 2] + s_t2p[tid * 4 + 3];
        const float qa = s_qap[tid * 4] + s_qap[tid * 4 + 1] +
                         s_qap[tid * 4 + 2] + s_qap[tid * 4 + 3];
        const float d  = disc[i0 + tid];
        s_disc[tid] = d;
        s_zc[tid]   = fmaf(-d, t2, bp[0]);
        s_qa[tid]   = qa;
    }
    asm volatile("cp.async.wait_group 0;\n" ::: "memory");
    __syncthreads();

    // ---- phase C: term1 = stuC @ qw^T, thread tile 4(b) x 8(i) ----
    // warp: tx = lane&7 -> 8 distinct qw rows (banks 4*tx, conflict-free),
    //       ty -> 4 distinct stuC rows, 8-lane broadcast each.
    const int tx = tid & 7;    // i = tx + 8v, v<8
    const int ty = tid >> 3;   // b = ty + 32u, u<4
    const float w2v = w2[0];
    const float b2v = b2[0];

    unsigned long long acc[4][8];
#pragma unroll
    for (int u = 0; u < 4; u++)
#pragma unroll
        for (int v = 0; v < 8; v++) acc[u][v] = 0ull;

    const float* pa = s_stuC + ty * SCS;
    const float* pq = s_qw   + tx * QWS;
#pragma unroll
    for (int c = 0; c < CONC; c += 4) {
        ulonglong2 a[4], q[8];
#pragma unroll
        for (int u = 0; u < 4; u++)
            a[u] = *(const ulonglong2*)(pa + u * 32 * SCS + c);
#pragma unroll
        for (int v = 0; v < 8; v++)
            q[v] = *(const ulonglong2*)(pq + v * 8 * QWS + c);
#pragma unroll
        for (int u = 0; u < 4; u++)
#pragma unroll
            for (int v = 0; v < 8; v++) {
                fma2(acc[u][v], a[u].x, q[v].x);
                fma2(acc[u][v], a[u].y, q[v].y);
            }
    }

    // ---- fused epilogue ----
#pragma unroll
    for (int u = 0; u < 4; u++) {
        const int b = ty + 32 * u;
        const float gs = s_gsu[b];
        float* orow = out + (size_t)b * ITEMS + i0;
#pragma unroll
        for (int v = 0; v < 8; v++) {
            const int il = tx + 8 * v;
            float lo, hi;
            asm("mov.b64 {%0, %1}, %2;" : "=f"(lo), "=f"(hi) : "l"(acc[u][v]));
            const float t1 = lo + hi;
            const float z  = fmaf(s_disc[il], t1, s_zc[il]);
            const float P  = sigmoidf(z);
            const float g1 = sigmoidf(gs + s_qa[il]);
            const float g2 = sigmoidf(fmaf(g1, w2v, b2v));
            orow[il] = g2 + (1.0f - g2) * P;
        }
    }
}

// ---------------------------------------------------------------------------
extern "C" void kernel_launch(void* const* d_in, const int* in_sizes, int n_in,
                              void* d_out, int out_size) {
    const int*   stu_list = (const int*)  d_in[0];
    const float* stu_emb  = (const float*)d_in[1];
    const float* item_emb = (const float*)d_in[2];
    const float* disc     = (const float*)d_in[3];
    const float* Q        = (const float*)d_in[4];
    const float* w1       = (const float*)d_in[5];
    const float* b1       = (const float*)d_in[6];
    const float* wp       = (const float*)d_in[7];
    const float* bp       = (const float*)d_in[8];
    const float* gw_stu   = (const float*)d_in[9];
    const float* gw_Q     = (const float*)d_in[10];
    const float* w2       = (const float*)d_in[11];
    const float* b2       = (const float*)d_in[12];
    float* out = (float*)d_out;

    stu_kernel<<<BATCH, 128>>>(stu_list, stu_emb, w1, b1, gw_stu);

    const size_t smem = (size_t)(BATCH * SCS + TI * QWS + CONC * W1S + TI * EMB +
                                 TI * 4 + TI * 4 + TI + TI + TI + BATCH) * sizeof(float);
    cudaFuncSetAttribute(main_kernel, cudaFuncAttributeMaxDynamicSharedMemorySize,
                         (int)smem);
    main_kernel<<<NBLK, 256, smem>>>(item_emb, disc, Q, w1, b1, wp, bp,
                                     gw_Q, w2, b2, out);
}

// round 3
// speedup vs baseline: 1.3269x; 1.0932x over previous
#include <cuda_runtime.h>
#include <cstdint>

#define BATCH 128
#define ITEMS 8000
#define CONC  128
#define EMB   32
#define TI    64              // items per block
#define NBLK  (ITEMS / TI)    // 125
#define SCS   132             // padded row stride (floats) for stuC in smem
#define QWS   132             // padded row stride for qw in smem
#define W1S   34              // padded row stride for w1

// scratch (allocation-free rule: __device__ globals)
__device__ float g_stuC[BATCH * CONC];
__device__ float g_gsu[BATCH];

__device__ __forceinline__ float sigmoidf(float x) {
    return __fdividef(1.0f, 1.0f + __expf(-x));
}

__device__ __forceinline__ void fma2(unsigned long long& acc,
                                     unsigned long long a,
                                     unsigned long long b) {
    asm("fma.rn.f32x2 %0, %1, %2, %0;" : "+l"(acc) : "l"(a), "l"(b));
}

// ---------------------------------------------------------------------------
// Kernel 1: stuC[b,c] = sigmoid(stu_emb[idx[b]] . w1[c] + b1[c]);  gsu[b]
// ---------------------------------------------------------------------------
__global__ void __launch_bounds__(128) stu_kernel(
    const int*   __restrict__ stu_list,
    const float* __restrict__ stu_emb,
    const float* __restrict__ w1,
    const float* __restrict__ b1,
    const float* __restrict__ gw_stu)
{
    __shared__ float s_w1[CONC * 33];
    __shared__ float s_emb[EMB];
    const int b = blockIdx.x;
    const int t = threadIdx.x;
    const int idx = stu_list[b] - 1;

    for (int j = t; j < CONC * EMB; j += 128)
        s_w1[(j >> 5) * 33 + (j & 31)] = w1[j];
    if (t < EMB) s_emb[t] = stu_emb[(size_t)idx * EMB + t];
    if (t == 0)  g_gsu[b] = gw_stu[idx];
    __syncthreads();

    float z = b1[t];
#pragma unroll
    for (int k = 0; k < EMB; k++) z = fmaf(s_emb[k], s_w1[t * 33 + k], z);
    g_stuC[b * CONC + t] = sigmoidf(z);
}

// ---------------------------------------------------------------------------
// Kernel 2, 512 threads per 64-item tile.
//   phase B: itemC + qw + per-item scalars (4 item-partitions x 128 concepts)
//   phase C: term1 = stuC @ qw^T, K-split in 2 groups of 256 threads
//            (thread tile 4b x 8i, f32x2, conflict-free LDS), then symmetric
//            partial exchange through smem + fused epilogue on both groups.
// ---------------------------------------------------------------------------
__global__ void __launch_bounds__(512, 1) main_kernel(
    const float* __restrict__ item_emb,
    const float* __restrict__ disc,
    const float* __restrict__ Q,
    const float* __restrict__ w1,
    const float* __restrict__ b1,
    const float* __restrict__ wp,
    const float* __restrict__ bp,
    const float* __restrict__ gw_Q,
    const float* __restrict__ w2,
    const float* __restrict__ b2,
    float* __restrict__ out)
{
    extern __shared__ float sm[];
    float* s_stuC = sm;                       // 128*132 (reused as s_red later)
    float* s_qw   = s_stuC + BATCH * SCS;     // 64*132
    float* s_w1   = s_qw   + TI * QWS;        // 128*34
    float* s_ie   = s_w1   + CONC * W1S;      // 64*32 linear
    float* s_t2p  = s_ie   + TI * EMB;        // 64*4
    float* s_qap  = s_t2p  + TI * 4;          // 64*4
    float* s_zc   = s_qap  + TI * 4;          // 64
    float* s_qa   = s_zc   + TI;              // 64
    float* s_disc = s_qa   + TI;              // 64
    float* s_gsu  = s_disc + TI;              // 128
    float* s_red  = s_stuC;                   // alias: 2*4096 partials

    const int tid = threadIdx.x;
    const int i0  = blockIdx.x * TI;

    // ---- async: g_stuC -> s_stuC (padded rows) ----
    for (int j = tid; j < BATCH * (CONC / 4); j += 512) {
        const int r  = j >> 5;
        const int c4 = j & 31;
        unsigned dst = (unsigned)__cvta_generic_to_shared(s_stuC + r * SCS + c4 * 4);
        const float* src = g_stuC + r * CONC + c4 * 4;
        asm volatile("cp.async.ca.shared.global [%0], [%1], 16;\n" :: "r"(dst), "l"(src));
    }
    asm volatile("cp.async.commit_group;\n" ::: "memory");

    // ---- synchronous smem fills ----
    for (int j = tid; j < CONC * EMB; j += 512)
        s_w1[(j >> 5) * W1S + (j & 31)] = w1[j];
    {
        const float4* src = (const float4*)(item_emb + (size_t)i0 * EMB);
        float4* dst = (float4*)s_ie;
        for (int j = tid; j < TI * EMB / 4; j += 512) dst[j] = src[j];
    }
    if (tid < BATCH) s_gsu[tid] = g_gsu[tid];
    __syncthreads();

    // ---- phase B ----
    {
        const int c     = tid & 127;
        const int p     = tid >> 7;       // 0..3
        const int lane  = tid & 31;
        const int chunk = c >> 5;
        const float wpc = wp[c];
        const float b1c = b1[c];
        const float gqc = gw_Q[c];

        unsigned long long w1r[16];
#pragma unroll
        for (int j = 0; j < 16; j++)
            w1r[j] = *(const unsigned long long*)(s_w1 + c * W1S + 2 * j);

        for (int ii = p; ii < TI; ii += 4) {
            const ulonglong2* ie = (const ulonglong2*)(s_ie + ii * EMB);
            unsigned long long za = 0ull, zb = 0ull;
#pragma unroll
            for (int k = 0; k < 8; k++) {
                ulonglong2 e = ie[k];
                fma2(za, e.x, w1r[2 * k]);
                fma2(zb, e.y, w1r[2 * k + 1]);
            }
            float la, ha, lb, hb;
            asm("mov.b64 {%0, %1}, %2;" : "=f"(la), "=f"(ha) : "l"(za));
            asm("mov.b64 {%0, %1}, %2;" : "=f"(lb), "=f"(hb) : "l"(zb));
            const float z  = (la + ha) + (lb + hb) + b1c;
            const float ic = sigmoidf(z);
            const float qv = Q[(size_t)(i0 + ii) * CONC + c];
            const float qwv = qv * wpc;
            s_qw[ii * QWS + c] = qwv;
            float prod = qwv * ic;
            float qadj = qv * gqc;
#pragma unroll
            for (int off = 16; off > 0; off >>= 1) {
                prod += __shfl_down_sync(0xffffffffu, prod, off);
                qadj += __shfl_down_sync(0xffffffffu, qadj, off);
            }
            if (lane == 0) {
                s_t2p[ii * 4 + chunk] = prod;
                s_qap[ii * 4 + chunk] = qadj;
            }
        }
    }
    __syncthreads();
    if (tid < TI) {
        const float t2 = s_t2p[tid * 4] + s_t2p[tid * 4 + 1] +
                         s_t2p[tid * 4 + 2] + s_t2p[tid * 4 + 3];
        const float qa = s_qap[tid * 4] + s_qap[tid * 4 + 1] +
                         s_qap[tid * 4 + 2] + s_qap[tid * 4 + 3];
        const float d  = disc[i0 + tid];
        s_disc[tid] = d;
        s_zc[tid]   = fmaf(-d, t2, bp[0]);
        s_qa[tid]   = qa;
    }
    asm volatile("cp.async.wait_group 0;\n" ::: "memory");
    __syncthreads();

    // ---- phase C: 2 K-groups of 256 threads, thread tile 4(b) x 8(i) ----
    const int g  = tid >> 8;        // K-group: c in [64g, 64g+64)
    const int t  = tid & 255;
    const int tx = t & 7;           // i = tx + 8v, v<8
    const int ty = t >> 3;          // b = ty + 32u, u<4

    unsigned long long acc[4][8];
#pragma unroll
    for (int u = 0; u < 4; u++)
#pragma unroll
        for (int v = 0; v < 8; v++) acc[u][v] = 0ull;

    const float* pa = s_stuC + ty * SCS + 64 * g;
    const float* pq = s_qw   + tx * QWS + 64 * g;
#pragma unroll
    for (int c = 0; c < 64; c += 4) {
        ulonglong2 a[4], q[8];
#pragma unroll
        for (int u = 0; u < 4; u++)
            a[u] = *(const ulonglong2*)(pa + u * 32 * SCS + c);
#pragma unroll
        for (int v = 0; v < 8; v++)
            q[v] = *(const ulonglong2*)(pq + v * 8 * QWS + c);
#pragma unroll
        for (int u = 0; u < 4; u++)
#pragma unroll
            for (int v = 0; v < 8; v++) {
                fma2(acc[u][v], a[u].x, q[v].x);
                fma2(acc[u][v], a[u].y, q[v].y);
            }
    }

    // reduce each acc to a float
    float t1[4][8];
#pragma unroll
    for (int u = 0; u < 4; u++)
#pragma unroll
        for (int v = 0; v < 8; v++) {
            float lo, hi;
            asm("mov.b64 {%0, %1}, %2;" : "=f"(lo), "=f"(hi) : "l"(acc[u][v]));
            t1[u][v] = lo + hi;
        }

    // ---- symmetric partial exchange through s_red (aliases s_stuC) ----
    // group g keeps u-half g*2..g*2+1, donates the other half.
    __syncthreads();   // everyone done reading s_stuC / s_qw
    {
        const int ud = (1 - g) * 2;   // donated u-halves
#pragma unroll
        for (int du = 0; du < 2; du++)
#pragma unroll
            for (int v = 0; v < 8; v++)
                s_red[((du * 32 + ty) + (1 - g) * 64) * 64 + tx + 8 * v] =
                    t1[ud + du][v];
    }
    __syncthreads();

    // ---- fused epilogue: group g finishes b-rows [64g, 64g+64) ----
    const float w2v = w2[0];
    const float b2v = b2[0];
#pragma unroll
    for (int du = 0; du < 2; du++) {
        const int u = g * 2 + du;
        const int b = ty + 32 * u;
        const float gs = s_gsu[b];
        float* orow = out + (size_t)b * ITEMS + i0;
#pragma unroll
        for (int v = 0; v < 8; v++) {
            const int il = tx + 8 * v;
            const float sum = t1[u][v] +
                s_red[((du * 32 + ty) + g * 64) * 64 + il];
            const float z  = fmaf(s_disc[il], sum, s_zc[il]);
            const float P  = sigmoidf(z);
            const float g1 = sigmoidf(gs + s_qa[il]);
            const float g2 = sigmoidf(fmaf(g1, w2v, b2v));
            orow[il] = g2 + (1.0f - g2) * P;
        }
    }
}

// ---------------------------------------------------------------------------
extern "C" void kernel_launch(void* const* d_in, const int* in_sizes, int n_in,
                              void* d_out, int out_size) {
    const int*   stu_list = (const int*)  d_in[0];
    const float* stu_emb  = (const float*)d_in[1];
    const float* item_emb = (const float*)d_in[2];
    const float* disc     = (const float*)d_in[3];
    const float* Q        = (const float*)d_in[4];
    const float* w1       = (const float*)d_in[5];
    const float* b1       = (const float*)d_in[6];
    const float* wp       = (const float*)d_in[7];
    const float* bp       = (const float*)d_in[8];
    const float* gw_stu   = (const float*)d_in[9];
    const float* gw_Q     = (const float*)d_in[10];
    const float* w2       = (const float*)d_in[11];
    const float* b2       = (const float*)d_in[12];
    float* out = (float*)d_out;

    stu_kernel<<<BATCH, 128>>>(stu_list, stu_emb, w1, b1, gw_stu);

    const size_t smem = (size_t)(BATCH * SCS + TI * QWS + CONC * W1S + TI * EMB +
                                 TI * 4 + TI * 4 + TI + TI + TI + BATCH) * sizeof(float);
    cudaFuncSetAttribute(main_kernel, cudaFuncAttributeMaxDynamicSharedMemorySize,
                         (int)smem);
    main_kernel<<<NBLK, 512, smem>>>(item_emb, disc, Q, w1, b1, wp, bp,
                                     gw_Q, w2, b2, out);
}

// round 5
// speedup vs baseline: 1.5814x; 1.1918x over previous
#include <cuda_runtime.h>
#include <cstdint>

#define BATCH 128
#define ITEMS 8000
#define CONC  128
#define EMB   32
#define TI    64
#define NBLK  (ITEMS / TI)    // 125
#define SCS   132             // padded stride: stuC rows
#define QWS   132             // padded stride: qw rows
#define W1S   34

// float-offset smem map
#define OFF_STUC 0            // 128*132
#define OFF_QW   16896        // 64*132  (aliased as stu_emb staging 128*32 first)
#define OFF_W1   25344        // 128*34
#define OFF_IE   29696        // 64*32
#define OFF_T2P  31744        // 64*4
#define OFF_QAP  32000        // 64*4
#define OFF_ZC   32256
#define OFF_QA   32320
#define OFF_DISC 32384
#define OFF_GSU  32448        // 128
#define OFF_IDX  32576        // 128 (int)
#define SMEM_FLOATS 32704
#define SMEM_BYTES  (SMEM_FLOATS * 4)

__device__ __forceinline__ float sigmoidf(float x) {
    return __fdividef(1.0f, 1.0f + __expf(-x));
}
__device__ __forceinline__ void fma2(unsigned long long& acc,
                                     unsigned long long a, unsigned long long b) {
    asm("fma.rn.f32x2 %0, %1, %2, %0;" : "+l"(acc) : "l"(a), "l"(b));
}
__device__ __forceinline__ float tf32_rna(float x) {
    uint32_t t;
    asm("cvt.rna.tf32.f32 %0, %1;" : "=r"(t) : "f"(x));
    return __uint_as_float(t);
}
__device__ __forceinline__ void mma_tf32(float* d, const uint32_t* a, const uint32_t* b) {
    asm("mma.sync.aligned.m16n8k8.row.col.f32.tf32.tf32.f32 "
        "{%0,%1,%2,%3}, {%4,%5,%6,%7}, {%8,%9}, {%0,%1,%2,%3};"
        : "+f"(d[0]), "+f"(d[1]), "+f"(d[2]), "+f"(d[3])
        : "r"(a[0]), "r"(a[1]), "r"(a[2]), "r"(a[3]), "r"(b[0]), "r"(b[1]));
}

// ---------------------------------------------------------------------------
// Single fused kernel, 512 threads per 64-item tile.
//   phase A: stuC[128,128] (recomputed per block, tf32-rounded)
//   phase B: itemC + qw (tf32) + per-item scalars
//   phase C: term1 = stuC @ qw^T via mma.sync tf32 m16n8k8, fused epilogue
// ---------------------------------------------------------------------------
__global__ void __launch_bounds__(512, 1) main_kernel(
    const int*   __restrict__ stu_list,
    const float* __restrict__ stu_emb,
    const float* __restrict__ item_emb,
    const float* __restrict__ disc,
    const float* __restrict__ Q,
    const float* __restrict__ w1,
    const float* __restrict__ b1,
    const float* __restrict__ wp,
    const float* __restrict__ bp,
    const float* __restrict__ gw_stu,
    const float* __restrict__ gw_Q,
    const float* __restrict__ w2,
    const float* __restrict__ b2,
    float* __restrict__ out)
{
    extern __shared__ float sm[];
    float* s_stuC = sm + OFF_STUC;
    float* s_qw   = sm + OFF_QW;
    float* s_emb2 = sm + OFF_QW;      // staging alias (dead before s_qw written)
    float* s_w1   = sm + OFF_W1;
    float* s_ie   = sm + OFF_IE;
    float* s_t2p  = sm + OFF_T2P;
    float* s_qap  = sm + OFF_QAP;
    float* s_zc   = sm + OFF_ZC;
    float* s_qa   = sm + OFF_QA;
    float* s_disc = sm + OFF_DISC;
    float* s_gsu  = sm + OFF_GSU;
    int*   s_idx  = (int*)(sm + OFF_IDX);

    const int tid  = threadIdx.x;
    const int wid  = tid >> 5;
    const int lane = tid & 31;
    const int i0   = blockIdx.x * TI;

    // ---- stage 0: student indices ----
    if (tid < BATCH) s_idx[tid] = stu_list[tid] - 1;
    __syncthreads();

    // ---- stage 1: fills ----
    for (int j = tid; j < CONC * EMB; j += 512)
        s_w1[(j >> 5) * W1S + (j & 31)] = w1[j];
    {   // item_emb tile
        const float4* src = (const float4*)(item_emb + (size_t)i0 * EMB);
        float4* dst = (float4*)s_ie;
        for (int j = tid; j < TI * EMB / 4; j += 512) dst[j] = src[j];
    }
    {   // gathered student embeddings -> s_emb2 [128 x 32]
        float4* dst = (float4*)s_emb2;
        for (int j = tid; j < BATCH * (EMB / 4); j += 512) {
            const int r = j >> 3, q = j & 7;
            dst[j] = ((const float4*)(stu_emb + (size_t)s_idx[r] * EMB))[q];
        }
    }
    if (tid < BATCH) s_gsu[tid] = gw_stu[s_idx[tid]];
    __syncthreads();

    // per-thread concept params + register-resident w1 row (phases A & B)
    const int c     = tid & 127;
    const int p     = tid >> 7;     // 0..3
    const int chunk = c >> 5;
    const float b1c = b1[c];
    unsigned long long w1r[16];
#pragma unroll
    for (int j = 0; j < 16; j++)
        w1r[j] = *(const unsigned long long*)(s_w1 + c * W1S + 2 * j);

    // ---- phase A: stuC ----
    for (int b = p; b < BATCH; b += 4) {
        const ulonglong2* eb = (const ulonglong2*)(s_emb2 + b * EMB);
        unsigned long long za = 0ull, zb = 0ull;
#pragma unroll
        for (int k = 0; k < 8; k++) {
            ulonglong2 e = eb[k];
            fma2(za, e.x, w1r[2 * k]);
            fma2(zb, e.y, w1r[2 * k + 1]);
        }
        float la, ha, lb, hb;
        asm("mov.b64 {%0, %1}, %2;" : "=f"(la), "=f"(ha) : "l"(za));
        asm("mov.b64 {%0, %1}, %2;" : "=f"(lb), "=f"(hb) : "l"(zb));
        s_stuC[b * SCS + c] = tf32_rna(sigmoidf((la + ha) + (lb + hb) + b1c));
    }
    __syncthreads();   // s_emb2 dead; s_qw may now be written

    // ---- phase B: itemC, qw, per-item scalars ----
    {
        const float wpc = wp[c];
        const float gqc = gw_Q[c];
        for (int ii = p; ii < TI; ii += 4) {
            const ulonglong2* ie = (const ulonglong2*)(s_ie + ii * EMB);
            unsigned long long za = 0ull, zb = 0ull;
#pragma unroll
            for (int k = 0; k < 8; k++) {
                ulonglong2 e = ie[k];
                fma2(za, e.x, w1r[2 * k]);
                fma2(zb, e.y, w1r[2 * k + 1]);
            }
            float la, ha, lb, hb;
            asm("mov.b64 {%0, %1}, %2;" : "=f"(la), "=f"(ha) : "l"(za));
            asm("mov.b64 {%0, %1}, %2;" : "=f"(lb), "=f"(hb) : "l"(zb));
            const float z  = (la + ha) + (lb + hb) + b1c;
            const float ic = sigmoidf(z);
            const float qv = Q[(size_t)(i0 + ii) * CONC + c];
            const float qwv = qv * wpc;
            s_qw[ii * QWS + c] = tf32_rna(qwv);

            float prod = qwv * ic;
            float qadj = qv * gqc;
#pragma unroll
            for (int off = 16; off > 0; off >>= 1) {
                prod += __shfl_down_sync(0xffffffffu, prod, off);
                qadj += __shfl_down_sync(0xffffffffu, qadj, off);
            }
            if (lane == 0) {
                s_t2p[ii * 4 + chunk] = prod;
                s_qap[ii * 4 + chunk] = qadj;
            }
        }
    }
    __syncthreads();
    if (tid < TI) {
        const float t2 = s_t2p[tid * 4] + s_t2p[tid * 4 + 1] +
                         s_t2p[tid * 4 + 2] + s_t2p[tid * 4 + 3];
        const float qa = s_qap[tid * 4] + s_qap[tid * 4 + 1] +
                         s_qap[tid * 4 + 2] + s_qap[tid * 4 + 3];
        const float d  = disc[i0 + tid];
        s_disc[tid] = d;
        s_zc[tid]   = fmaf(-d, t2, bp[0]);
        s_qa[tid]   = qa;
    }
    __syncthreads();

    // ---- phase C: mma.sync tf32. warp tile 32(b) x 16(i) ----
    const int wm  = wid & 3;       // rows 32*wm .. +32
    const int wn  = wid >> 2;      // cols 16*wn .. +16
    const int gid = lane >> 2;
    const int tig = lane & 3;

    float acc[2][2][4];
#pragma unroll
    for (int mi = 0; mi < 2; mi++)
#pragma unroll
        for (int ni = 0; ni < 2; ni++)
#pragma unroll
            for (int r = 0; r < 4; r++) acc[mi][ni][r] = 0.0f;

    const float* paBase = s_stuC + (32 * wm + gid) * SCS + tig;
    const float* pbBase = s_qw   + (16 * wn + gid) * QWS + tig;
#pragma unroll
    for (int k0 = 0; k0 < CONC; k0 += 8) {
        uint32_t a[2][4], bf[2][2];
#pragma unroll
        for (int mi = 0; mi < 2; mi++) {
            const float* pa = paBase + 16 * mi * SCS + k0;
            a[mi][0] = __float_as_uint(pa[0]);
            a[mi][1] = __float_as_uint(pa[8 * SCS]);
            a[mi][2] = __float_as_uint(pa[4]);
            a[mi][3] = __float_as_uint(pa[8 * SCS + 4]);
        }
#pragma unroll
        for (int ni = 0; ni < 2; ni++) {
            const float* pb = pbBase + 8 * ni * QWS + k0;
            bf[ni][0] = __float_as_uint(pb[0]);
            bf[ni][1] = __float_as_uint(pb[4]);
        }
#pragma unroll
        for (int mi = 0; mi < 2; mi++)
#pragma unroll
            for (int ni = 0; ni < 2; ni++)
                mma_tf32(acc[mi][ni], a[mi], bf[ni]);
    }

    // ---- fused epilogue ----
    const float w2v = w2[0];
    const float b2v = b2[0];
#pragma unroll
    for (int mi = 0; mi < 2; mi++)
#pragma unroll
        for (int h = 0; h < 2; h++) {
            const int row = 32 * wm + 16 * mi + 8 * h + gid;
            const float gs = s_gsu[row];
            float* orow = out + (size_t)row * ITEMS + i0;
#pragma unroll
            for (int ni = 0; ni < 2; ni++) {
                const int col = 16 * wn + 8 * ni + 2 * tig;
                float res[2];
#pragma unroll
                for (int e = 0; e < 2; e++) {
                    const int il = col + e;
                    const float t1 = acc[mi][ni][2 * h + e];
                    const float z  = fmaf(s_disc[il], t1, s_zc[il]);
                    const float P  = sigmoidf(z);
                    const float g1 = sigmoidf(gs + s_qa[il]);
                    const float g2 = sigmoidf(fmaf(g1, w2v, b2v));
                    res[e] = g2 + (1.0f - g2) * P;
                }
                *(float2*)(orow + col) = make_float2(res[0], res[1]);
            }
        }
}

// ---------------------------------------------------------------------------
extern "C" void kernel_launch(void* const* d_in, const int* in_sizes, int n_in,
                              void* d_out, int out_size) {
    const int*   stu_list = (const int*)  d_in[0];
    const float* stu_emb  = (const float*)d_in[1];
    const float* item_emb = (const float*)d_in[2];
    const float* disc     = (const float*)d_in[3];
    const float* Q        = (const float*)d_in[4];
    const float* w1       = (const float*)d_in[5];
    const float* b1       = (const float*)d_in[6];
    const float* wp       = (const float*)d_in[7];
    const float* bp       = (const float*)d_in[8];
    const float* gw_stu   = (const float*)d_in[9];
    const float* gw_Q     = (const float*)d_in[10];
    const float* w2       = (const float*)d_in[11];
    const float* b2       = (const float*)d_in[12];
    float* out = (float*)d_out;

    cudaFuncSetAttribute(main_kernel, cudaFuncAttributeMaxDynamicSharedMemorySize,
                         SMEM_BYTES);
    main_kernel<<<NBLK, 512, SMEM_BYTES>>>(stu_list, stu_emb, item_emb, disc, Q,
                                           w1, b1, wp, bp, gw_stu, gw_Q, w2, b2,
                                           out);
}

// round 6
// speedup vs baseline: 1.7580x; 1.1117x over previous
#include <cuda_runtime.h>
#include <cstdint>

#define BATCH 128
#define ITEMS 8000
#define CONC  128
#define EMB   32
#define TI    64
#define NBLK  (ITEMS / TI)    // 125
#define SCS   132             // padded stride: stuC rows
#define QWS   132             // padded stride: qw rows
#define W1S   34

// float-offset smem map
#define OFF_STUC 0            // 128*132
#define OFF_QW   16896        // 64*132
#define OFF_W1   25344        // 128*34
#define OFF_IE   29696        // 64*32
#define OFF_T2P  31744        // 64*4
#define OFF_QAP  32000        // 64*4
#define OFF_ZC   32256
#define OFF_QA   32320
#define OFF_DISC 32384
#define OFF_GSU  32448        // 128
#define SMEM_FLOATS 32576
#define SMEM_BYTES  (SMEM_FLOATS * 4)

__device__ float g_stuC[BATCH * CONC];   // tf32-rounded sigmoid values
__device__ float g_gsu[BATCH];

__device__ __forceinline__ float sigmoidf(float x) {      // accurate (2 MUFU)
    return __fdividef(1.0f, 1.0f + __expf(-x));
}
__device__ __forceinline__ float sigt(float x) {          // fast (1 MUFU)
    float t;
    asm("tanh.approx.f32 %0, %1;" : "=f"(t) : "f"(x * 0.5f));
    return fmaf(0.5f, t, 0.5f);
}
__device__ __forceinline__ void fma2(unsigned long long& acc,
                                     unsigned long long a, unsigned long long b) {
    asm("fma.rn.f32x2 %0, %1, %2, %0;" : "+l"(acc) : "l"(a), "l"(b));
}
__device__ __forceinline__ float tf32_rna(float x) {
    uint32_t t;
    asm("cvt.rna.tf32.f32 %0, %1;" : "=r"(t) : "f"(x));
    return __uint_as_float(t);
}
__device__ __forceinline__ void mma_tf32(float* d, const uint32_t* a, const uint32_t* b) {
    asm("mma.sync.aligned.m16n8k8.row.col.f32.tf32.tf32.f32 "
        "{%0,%1,%2,%3}, {%4,%5,%6,%7}, {%8,%9}, {%0,%1,%2,%3};"
        : "+f"(d[0]), "+f"(d[1]), "+f"(d[2]), "+f"(d[3])
        : "r"(a[0]), "r"(a[1]), "r"(a[2]), "r"(a[3]), "r"(b[0]), "r"(b[1]));
}

// ---------------------------------------------------------------------------
// Kernel 1: g_stuC[b,c] = tf32(sigmoid(stu_emb[idx[b]] . w1[c] + b1[c]))
// ---------------------------------------------------------------------------
__global__ void __launch_bounds__(128) stu_kernel(
    const int*   __restrict__ stu_list,
    const float* __restrict__ stu_emb,
    const float* __restrict__ w1,
    const float* __restrict__ b1,
    const float* __restrict__ gw_stu)
{
    __shared__ float s_w1[CONC * 33];
    __shared__ float s_emb[EMB];
    const int b = blockIdx.x;
    const int t = threadIdx.x;
    const int idx = stu_list[b] - 1;

    for (int j = t; j < CONC * EMB; j += 128)
        s_w1[(j >> 5) * 33 + (j & 31)] = w1[j];
    if (t < EMB) s_emb[t] = stu_emb[(size_t)idx * EMB + t];
    if (t == 0)  g_gsu[b] = gw_stu[idx];
    __syncthreads();

    float z = b1[t];
#pragma unroll
    for (int k = 0; k < EMB; k++) z = fmaf(s_emb[k], s_w1[t * 33 + k], z);
    g_stuC[b * CONC + t] = tf32_rna(sigmoidf(z));
}

// ---------------------------------------------------------------------------
// Kernel 2, 512 threads per 64-item tile.
//   phase B: itemC + qw (tf32) + per-item scalars (tanh sigmoid)
//   phase C: term1 = stuC @ qw^T via mma.sync tf32, fused epilogue (tanh)
// ---------------------------------------------------------------------------
__global__ void __launch_bounds__(512, 1) main_kernel(
    const float* __restrict__ item_emb,
    const float* __restrict__ disc,
    const float* __restrict__ Q,
    const float* __restrict__ w1,
    const float* __restrict__ b1,
    const float* __restrict__ wp,
    const float* __restrict__ bp,
    const float* __restrict__ gw_Q,
    const float* __restrict__ w2,
    const float* __restrict__ b2,
    float* __restrict__ out)
{
    extern __shared__ float sm[];
    float* s_stuC = sm + OFF_STUC;
    float* s_qw   = sm + OFF_QW;
    float* s_w1   = sm + OFF_W1;
    float* s_ie   = sm + OFF_IE;
    float* s_t2p  = sm + OFF_T2P;
    float* s_qap  = sm + OFF_QAP;
    float* s_zc   = sm + OFF_ZC;
    float* s_qa   = sm + OFF_QA;
    float* s_disc = sm + OFF_DISC;
    float* s_gsu  = sm + OFF_GSU;

    const int tid  = threadIdx.x;
    const int wid  = tid >> 5;
    const int lane = tid & 31;
    const int i0   = blockIdx.x * TI;

    // ---- async: g_stuC -> s_stuC (padded rows), overlapped with phase B ----
    for (int j = tid; j < BATCH * (CONC / 4); j += 512) {
        const int r  = j >> 5;
        const int c4 = j & 31;
        unsigned dst = (unsigned)__cvta_generic_to_shared(s_stuC + r * SCS + c4 * 4);
        const float* src = g_stuC + r * CONC + c4 * 4;
        asm volatile("cp.async.ca.shared.global [%0], [%1], 16;\n" :: "r"(dst), "l"(src));
    }
    asm volatile("cp.async.commit_group;\n" ::: "memory");

    // ---- synchronous fills ----
    for (int j = tid; j < CONC * EMB; j += 512)
        s_w1[(j >> 5) * W1S + (j & 31)] = w1[j];
    {
        const float4* src = (const float4*)(item_emb + (size_t)i0 * EMB);
        float4* dst = (float4*)s_ie;
        for (int j = tid; j < TI * EMB / 4; j += 512) dst[j] = src[j];
    }
    if (tid < BATCH) s_gsu[tid] = g_gsu[tid];
    __syncthreads();

    // ---- phase B: itemC, qw (tf32), per-item scalars ----
    {
        const int c     = tid & 127;
        const int p     = tid >> 7;     // 0..3
        const int chunk = c >> 5;
        const float wpc = wp[c];
        const float b1c = b1[c];
        const float gqc = gw_Q[c];

        unsigned long long w1r[16];
#pragma unroll
        for (int j = 0; j < 16; j++)
            w1r[j] = *(const unsigned long long*)(s_w1 + c * W1S + 2 * j);

        for (int ii = p; ii < TI; ii += 4) {
            const ulonglong2* ie = (const ulonglong2*)(s_ie + ii * EMB);
            unsigned long long za = 0ull, zb = 0ull;
#pragma unroll
            for (int k = 0; k < 8; k++) {
                ulonglong2 e = ie[k];
                fma2(za, e.x, w1r[2 * k]);
                fma2(zb, e.y, w1r[2 * k + 1]);
            }
            float la, ha, lb, hb;
            asm("mov.b64 {%0, %1}, %2;" : "=f"(la), "=f"(ha) : "l"(za));
            asm("mov.b64 {%0, %1}, %2;" : "=f"(lb), "=f"(hb) : "l"(zb));
            const float z  = (la + ha) + (lb + hb) + b1c;
            const float ic = sigt(z);
            const float qv = Q[(size_t)(i0 + ii) * CONC + c];
            const float qwv = qv * wpc;
            s_qw[ii * QWS + c] = tf32_rna(qwv);

            float prod = qwv * ic;
            float qadj = qv * gqc;
#pragma unroll
            for (int off = 16; off > 0; off >>= 1) {
                prod += __shfl_down_sync(0xffffffffu, prod, off);
                qadj += __shfl_down_sync(0xffffffffu, qadj, off);
            }
            if (lane == 0) {
                s_t2p[ii * 4 + chunk] = prod;
                s_qap[ii * 4 + chunk] = qadj;
            }
        }
    }
    __syncthreads();
    if (tid < TI) {
        const float t2 = s_t2p[tid * 4] + s_t2p[tid * 4 + 1] +
                         s_t2p[tid * 4 + 2] + s_t2p[tid * 4 + 3];
        const float qa = s_qap[tid * 4] + s_qap[tid * 4 + 1] +
                         s_qap[tid * 4 + 2] + s_qap[tid * 4 + 3];
        const float d  = disc[i0 + tid];
        s_disc[tid] = d;
        s_zc[tid]   = fmaf(-d, t2, bp[0]);
        s_qa[tid]   = qa;
    }
    asm volatile("cp.async.wait_group 0;\n" ::: "memory");
    __syncthreads();

    // ---- phase C: mma.sync tf32. warp tile 32(b) x 16(i) ----
    const int wm  = wid & 3;
    const int wn  = wid >> 2;
    const int gid = lane >> 2;
    const int tig = lane & 3;

    float acc[2][2][4];
#pragma unroll
    for (int mi = 0; mi < 2; mi++)
#pragma unroll
        for (int ni = 0; ni < 2; ni++)
#pragma unroll
            for (int r = 0; r < 4; r++) acc[mi][ni][r] = 0.0f;

    const float* paBase = s_stuC + (32 * wm + gid) * SCS + tig;
    const float* pbBase = s_qw   + (16 * wn + gid) * QWS + tig;
#pragma unroll
    for (int k0 = 0; k0 < CONC; k0 += 8) {
        uint32_t a[2][4], bf[2][2];
#pragma unroll
        for (int mi = 0; mi < 2; mi++) {
            const float* pa = paBase + 16 * mi * SCS + k0;
            a[mi][0] = __float_as_uint(pa[0]);
            a[mi][1] = __float_as_uint(pa[8 * SCS]);
            a[mi][2] = __float_as_uint(pa[4]);
            a[mi][3] = __float_as_uint(pa[8 * SCS + 4]);
        }
#pragma unroll
        for (int ni = 0; ni < 2; ni++) {
            const float* pb = pbBase + 8 * ni * QWS + k0;
            bf[ni][0] = __float_as_uint(pb[0]);
            bf[ni][1] = __float_as_uint(pb[4]);
        }
#pragma unroll
        for (int mi = 0; mi < 2; mi++)
#pragma unroll
            for (int ni = 0; ni < 2; ni++)
                mma_tf32(acc[mi][ni], a[mi], bf[ni]);
    }

    // ---- fused epilogue (tanh sigmoids: 3 MUFU per output) ----
    const float w2v = w2[0];
    const float b2v = b2[0];
#pragma unroll
    for (int mi = 0; mi < 2; mi++)
#pragma unroll
        for (int h = 0; h < 2; h++) {
            const int row = 32 * wm + 16 * mi + 8 * h + gid;
            const float gs = s_gsu[row];
            float* orow = out + (size_t)row * ITEMS + i0;
#pragma unroll
            for (int ni = 0; ni < 2; ni++) {
                const int col = 16 * wn + 8 * ni + 2 * tig;
                float res[2];
#pragma unroll
                for (int e = 0; e < 2; e++) {
                    const int il = col + e;
                    const float t1 = acc[mi][ni][2 * h + e];
                    const float z  = fmaf(s_disc[il], t1, s_zc[il]);
                    const float P  = sigt(z);
                    const float g1 = sigt(gs + s_qa[il]);
                    const float g2 = sigt(fmaf(g1, w2v, b2v));
                    res[e] = g2 + (1.0f - g2) * P;
                }
                *(float2*)(orow + col) = make_float2(res[0], res[1]);
            }
        }
}

// ---------------------------------------------------------------------------
extern "C" void kernel_launch(void* const* d_in, const int* in_sizes, int n_in,
                              void* d_out, int out_size) {
    const int*   stu_list = (const int*)  d_in[0];
    const float* stu_emb  = (const float*)d_in[1];
    const float* item_emb = (const float*)d_in[2];
    const float* disc     = (const float*)d_in[3];
    const float* Q        = (const float*)d_in[4];
    const float* w1       = (const float*)d_in[5];
    const float* b1       = (const float*)d_in[6];
    const float* wp       = (const float*)d_in[7];
    const float* bp       = (const float*)d_in[8];
    const float* gw_stu   = (const float*)d_in[9];
    const float* gw_Q     = (const float*)d_in[10];
    const float* w2       = (const float*)d_in[11];
    const float* b2       = (const float*)d_in[12];
    float* out = (float*)d_out;

    stu_kernel<<<BATCH, 128>>>(stu_list, stu_emb, w1, b1, gw_stu);

    cudaFuncSetAttribute(main_kernel, cudaFuncAttributeMaxDynamicSharedMemorySize,
                         SMEM_BYTES);
    main_kernel<<<NBLK, 512, SMEM_BYTES>>>(item_emb, disc, Q, w1, b1, wp, bp,
                                           gw_Q, w2, b2, out);
}

// round 7
// speedup vs baseline: 1.9715x; 1.1214x over previous
#include <cuda_runtime.h>
#include <cstdint>

#define BATCH 128
#define ITEMS 8000
#define CONC  128
#define EMB   32
#define TI    64
#define NBLK  (ITEMS / TI)    // 125
#define SCS   132             // stuC row stride (phase C conflict-free)
#define QWS   132             // qw row stride (phase C conflict-free)
#define W1S   36              // w1 row stride  (phase B conflict-free)
#define IES   36              // item_emb row stride
#define QS    136             // Q tile row stride

// float-offset smem map
#define OFF_STUC 0            // 128*132 = 16896
#define OFF_QW   16896        // 64*132  = 8448
#define OFF_W1   25344        // 128*36  = 4608
#define OFF_IE   29952        // 64*36   = 2304
#define OFF_Q    32256        // 64*136  = 8704
#define OFF_B1   40960        // 128
#define OFF_WP   41088        // 128
#define OFF_GQ   41216        // 128
#define OFF_ZC   41344        // 64
#define OFF_QA   41408        // 64
#define OFF_DISC 41472        // 64
#define OFF_GSU  41536        // 128
#define SMEM_FLOATS 41664
#define SMEM_BYTES  (SMEM_FLOATS * 4)

__device__ float g_stuC[BATCH * CONC];   // tf32-rounded sigmoid values
__device__ float g_gsu[BATCH];

__device__ __forceinline__ float sigmoidf(float x) {      // accurate (2 MUFU)
    return __fdividef(1.0f, 1.0f + __expf(-x));
}
__device__ __forceinline__ float sigt(float x) {          // fast (1 MUFU)
    float t;
    asm("tanh.approx.f32 %0, %1;" : "=f"(t) : "f"(x * 0.5f));
    return fmaf(0.5f, t, 0.5f);
}
__device__ __forceinline__ void fma2(unsigned long long& acc,
                                     unsigned long long a, unsigned long long b) {
    asm("fma.rn.f32x2 %0, %1, %2, %0;" : "+l"(acc) : "l"(a), "l"(b));
}
__device__ __forceinline__ float tf32_rna(float x) {
    uint32_t t;
    asm("cvt.rna.tf32.f32 %0, %1;" : "=r"(t) : "f"(x));
    return __uint_as_float(t);
}
__device__ __forceinline__ void mma_tf32(float* d, const uint32_t* a, const uint32_t* b) {
    asm("mma.sync.aligned.m16n8k8.row.col.f32.tf32.tf32.f32 "
        "{%0,%1,%2,%3}, {%4,%5,%6,%7}, {%8,%9}, {%0,%1,%2,%3};"
        : "+f"(d[0]), "+f"(d[1]), "+f"(d[2]), "+f"(d[3])
        : "r"(a[0]), "r"(a[1]), "r"(a[2]), "r"(a[3]), "r"(b[0]), "r"(b[1]));
}
__device__ __forceinline__ void cp16(float* dst_smem, const float* src) {
    unsigned d = (unsigned)__cvta_generic_to_shared(dst_smem);
    asm volatile("cp.async.ca.shared.global [%0], [%1], 16;\n" :: "r"(d), "l"(src));
}

// ---------------------------------------------------------------------------
// Kernel 1: g_stuC[b,c] = tf32(sigmoid(stu_emb[idx[b]] . w1[c] + b1[c]))
// ---------------------------------------------------------------------------
__global__ void __launch_bounds__(128) stu_kernel(
    const int*   __restrict__ stu_list,
    const float* __restrict__ stu_emb,
    const float* __restrict__ w1,
    const float* __restrict__ b1,
    const float* __restrict__ gw_stu)
{
    __shared__ float s_w1[CONC * 33];
    __shared__ float s_emb[EMB];
    const int b = blockIdx.x;
    const int t = threadIdx.x;
    const int idx = stu_list[b] - 1;

    for (int j = t; j < CONC * EMB; j += 128)
        s_w1[(j >> 5) * 33 + (j & 31)] = w1[j];
    if (t < EMB) s_emb[t] = stu_emb[(size_t)idx * EMB + t];
    if (t == 0)  g_gsu[b] = gw_stu[idx];
    __syncthreads();

    float z = b1[t];
#pragma unroll
    for (int k = 0; k < EMB; k++) z = fmaf(s_emb[k], s_w1[t * 33 + k], z);
    g_stuC[b * CONC + t] = tf32_rna(sigmoidf(z));
}

// ---------------------------------------------------------------------------
// Kernel 2, 512 threads per 64-item tile.
//   prefetch: everything via cp.async (group0: phase-B data, group1: stuC)
//   phase B: 8 threads/item x 16 interleaved concepts, register reductions
//   phase C: term1 = stuC @ qw^T via mma.sync tf32, fused epilogue (tanh)
// ---------------------------------------------------------------------------
__global__ void __launch_bounds__(512, 1) main_kernel(
    const float* __restrict__ item_emb,
    const float* __restrict__ disc,
    const float* __restrict__ Q,
    const float* __restrict__ w1,
    const float* __restrict__ b1,
    const float* __restrict__ wp,
    const float* __restrict__ bp,
    const float* __restrict__ gw_Q,
    const float* __restrict__ w2,
    const float* __restrict__ b2,
    float* __restrict__ out)
{
    extern __shared__ float sm[];
    float* s_stuC = sm + OFF_STUC;
    float* s_qw   = sm + OFF_QW;
    float* s_w1   = sm + OFF_W1;
    float* s_ie   = sm + OFF_IE;
    float* s_Q    = sm + OFF_Q;
    float* s_b1   = sm + OFF_B1;
    float* s_wp   = sm + OFF_WP;
    float* s_gq   = sm + OFF_GQ;
    float* s_zc   = sm + OFF_ZC;
    float* s_qa   = sm + OFF_QA;
    float* s_disc = sm + OFF_DISC;
    float* s_gsu  = sm + OFF_GSU;

    const int tid  = threadIdx.x;
    const int wid  = tid >> 5;
    const int lane = tid & 31;
    const int i0   = blockIdx.x * TI;

    // ---- group 0: everything phase B needs ----
    for (int j = tid; j < CONC * 8; j += 512)           // w1: 1024 chunks
        cp16(s_w1 + (j >> 3) * W1S + (j & 7) * 4, w1 + j * 4);
    for (int j = tid; j < TI * 8; j += 512)             // item_emb: 512 chunks
        cp16(s_ie + (j >> 3) * IES + (j & 7) * 4,
             item_emb + (size_t)i0 * EMB + j * 4);
    for (int j = tid; j < TI * 32; j += 512)            // Q tile: 2048 chunks
        cp16(s_Q + (j >> 5) * QS + (j & 31) * 4,
             Q + (size_t)(i0 + (j >> 5)) * CONC + (j & 31) * 4);
    if (tid < 32)  cp16(s_b1 + tid * 4, b1 + tid * 4);
    else if (tid < 64)  cp16(s_wp + (tid - 32) * 4, wp + (tid - 32) * 4);
    else if (tid < 96)  cp16(s_gq + (tid - 64) * 4, gw_Q + (tid - 64) * 4);
    else if (tid < 112) cp16(s_disc + (tid - 96) * 4, disc + i0 + (tid - 96) * 4);
    else if (tid < 144) cp16(s_gsu + (tid - 112) * 4, g_gsu + (tid - 112) * 4);
    asm volatile("cp.async.commit_group;\n" ::: "memory");

    // ---- group 1: stuC (only needed by phase C) ----
    for (int j = tid; j < BATCH * 32; j += 512)
        cp16(s_stuC + (j >> 5) * SCS + (j & 31) * 4, g_stuC + j * 4);
    asm volatile("cp.async.commit_group;\n" ::: "memory");

    const float bpv = bp[0];
    asm volatile("cp.async.wait_group 1;\n" ::: "memory");
    __syncthreads();

    // ---- phase B: item ii = tid>>3, concepts c = (tid&7) + 8s ----
    {
        const int ii = tid >> 3;
        const int cr = tid & 7;

        ulonglong2 ier[8];
        const ulonglong2* iep = (const ulonglong2*)(s_ie + ii * IES);
#pragma unroll
        for (int k = 0; k < 8; k++) ier[k] = iep[k];

        float prod = 0.0f, qa = 0.0f;
#pragma unroll 4
        for (int s = 0; s < 16; s++) {
            const int c = cr + 8 * s;
            const ulonglong2* wr = (const ulonglong2*)(s_w1 + c * W1S);
            unsigned long long za = 0ull, zb = 0ull;
#pragma unroll
            for (int k = 0; k < 8; k++) {
                ulonglong2 w = wr[k];
                fma2(za, ier[k].x, w.x);
                fma2(zb, ier[k].y, w.y);
            }
            float la, ha, lb, hb;
            asm("mov.b64 {%0, %1}, %2;" : "=f"(la), "=f"(ha) : "l"(za));
            asm("mov.b64 {%0, %1}, %2;" : "=f"(lb), "=f"(hb) : "l"(zb));
            const float z  = (la + ha) + (lb + hb) + s_b1[c];
            const float ic = sigt(z);
            const float qv = s_Q[ii * QS + c];
            const float qwv = qv * s_wp[c];
            s_qw[ii * QWS + c] = tf32_rna(qwv);
            prod = fmaf(qwv, ic, prod);
            qa   = fmaf(qv, s_gq[c], qa);
        }
#pragma unroll
        for (int off = 4; off > 0; off >>= 1) {
            prod += __shfl_down_sync(0xffffffffu, prod, off, 8);
            qa   += __shfl_down_sync(0xffffffffu, qa,   off, 8);
        }
        if (cr == 0) {
            s_zc[ii] = fmaf(-s_disc[ii], prod, bpv);
            s_qa[ii] = qa;
        }
    }
    asm volatile("cp.async.wait_group 0;\n" ::: "memory");
    __syncthreads();

    // ---- phase C: mma.sync tf32. warp tile 32(b) x 16(i) ----
    const int wm  = wid & 3;
    const int wn  = wid >> 2;
    const int gid = lane >> 2;
    const int tig = lane & 3;

    float acc[2][2][4];
#pragma unroll
    for (int mi = 0; mi < 2; mi++)
#pragma unroll
        for (int ni = 0; ni < 2; ni++)
#pragma unroll
            for (int r = 0; r < 4; r++) acc[mi][ni][r] = 0.0f;

    const float* paBase = s_stuC + (32 * wm + gid) * SCS + tig;
    const float* pbBase = s_qw   + (16 * wn + gid) * QWS + tig;
#pragma unroll
    for (int k0 = 0; k0 < CONC; k0 += 8) {
        uint32_t a[2][4], bf[2][2];
#pragma unroll
        for (int mi = 0; mi < 2; mi++) {
            const float* pa = paBase + 16 * mi * SCS + k0;
            a[mi][0] = __float_as_uint(pa[0]);
            a[mi][1] = __float_as_uint(pa[8 * SCS]);
            a[mi][2] = __float_as_uint(pa[4]);
            a[mi][3] = __float_as_uint(pa[8 * SCS + 4]);
        }
#pragma unroll
        for (int ni = 0; ni < 2; ni++) {
            const float* pb = pbBase + 8 * ni * QWS + k0;
            bf[ni][0] = __float_as_uint(pb[0]);
            bf[ni][1] = __float_as_uint(pb[4]);
        }
#pragma unroll
        for (int mi = 0; mi < 2; mi++)
#pragma unroll
            for (int ni = 0; ni < 2; ni++)
                mma_tf32(acc[mi][ni], a[mi], bf[ni]);
    }

    // ---- fused epilogue (tanh sigmoids: 3 MUFU per output) ----
    const float w2v = w2[0];
    const float b2v = b2[0];
#pragma unroll
    for (int mi = 0; mi < 2; mi++)
#pragma unroll
        for (int h = 0; h < 2; h++) {
            const int row = 32 * wm + 16 * mi + 8 * h + gid;
            const float gs = s_gsu[row];
            float* orow = out + (size_t)row * ITEMS + i0;
#pragma unroll
            for (int ni = 0; ni < 2; ni++) {
                const int col = 16 * wn + 8 * ni + 2 * tig;
                float res[2];
#pragma unroll
                for (int e = 0; e < 2; e++) {
                    const int il = col + e;
                    const float t1 = acc[mi][ni][2 * h + e];
                    const float z  = fmaf(s_disc[il], t1, s_zc[il]);
                    const float P  = sigt(z);
                    const float g1 = sigt(gs + s_qa[il]);
                    const float g2 = sigt(fmaf(g1, w2v, b2v));
                    res[e] = g2 + (1.0f - g2) * P;
                }
                *(float2*)(orow + col) = make_float2(res[0], res[1]);
            }
        }
}

// ---------------------------------------------------------------------------
extern "C" void kernel_launch(void* const* d_in, const int* in_sizes, int n_in,
                              void* d_out, int out_size) {
    const int*   stu_list = (const int*)  d_in[0];
    const float* stu_emb  = (const float*)d_in[1];
    const float* item_emb = (const float*)d_in[2];
    const float* disc     = (const float*)d_in[3];
    const float* Q        = (const float*)d_in[4];
    const float* w1       = (const float*)d_in[5];
    const float* b1       = (const float*)d_in[6];
    const float* wp       = (const float*)d_in[7];
    const float* bp       = (const float*)d_in[8];
    const float* gw_stu   = (const float*)d_in[9];
    const float* gw_Q     = (const float*)d_in[10];
    const float* w2       = (const float*)d_in[11];
    const float* b2       = (const float*)d_in[12];
    float* out = (float*)d_out;

    stu_kernel<<<BATCH, 128>>>(stu_list, stu_emb, w1, b1, gw_stu);

    cudaFuncSetAttribute(main_kernel, cudaFuncAttributeMaxDynamicSharedMemorySize,
                         SMEM_BYTES);
    main_kernel<<<NBLK, 512, SMEM_BYTES>>>(item_emb, disc, Q, w1, b1, wp, bp,
                                           gw_Q, w2, b2, out);
}